// round 5
// baseline (speedup 1.0000x reference)
#include <cuda_runtime.h>
#include <cstdint>

#define BB    8192
#define NN    40
#define FF    256
#define NBLK  4
#define BLKSZ 10
#define NF    (NN * FF)          // 10240
#define EPSF  1e-5f
#define NSPLIT 64                // batch splits for stats reduction

// Scratch (static __device__ allocations, allowed by harness rules)
__device__ float g_T[(size_t)BB * NN * FF];          // 335 MB: block-mixed input
__device__ float g_psum[NSPLIT * NF];                // 2.6 MB: partial sums
__device__ float g_psumsq[NSPLIT * NF];              // 2.6 MB: partial sum-squares
__device__ float g_scale[NF];
__device__ float g_shift[NF];

__device__ __forceinline__ uint32_t f2tf32(float f) {
    uint32_t r;
    asm("cvt.rna.tf32.f32 %0, %1;" : "=r"(r) : "f"(f));
    return r;
}

// ---------------------------------------------------------------------------
// K1: T[b, s+n, f] = sum_j adj[b, s+n, s+j] * X[b, s+j, f]   (block-diag mix)
// grid (B, NBLK), 256 threads (one per f)
// ---------------------------------------------------------------------------
__global__ void k_blockmix(const float* __restrict__ input,
                           const float* __restrict__ adj) {
    __shared__ float a_s[BLKSZ][BLKSZ];
    const int b   = blockIdx.x;
    const int blk = blockIdx.y;
    const int s   = blk * BLKSZ;
    const int f   = threadIdx.x;

    if (f < BLKSZ * BLKSZ) {
        int n = f / BLKSZ, j = f % BLKSZ;
        a_s[n][j] = adj[((size_t)b * NN + s + n) * NN + s + j];
    }
    __syncthreads();

    float x[BLKSZ];
#pragma unroll
    for (int j = 0; j < BLKSZ; j++)
        x[j] = input[((size_t)b * NN + s + j) * FF + f];

#pragma unroll
    for (int n = 0; n < BLKSZ; n++) {
        float acc = 0.f;
#pragma unroll
        for (int j = 0; j < BLKSZ; j++)
            acc = fmaf(a_s[n][j], x[j], acc);
        g_T[((size_t)b * NN + s + n) * FF + f] = acc;
    }
}

// ---------------------------------------------------------------------------
// K2: Y = T @ W  [327680 x 256] @ [256 x 256], written directly to d_out.
// tf32 tensor-core GEMM via mma.sync.m16n8k8 (fp32 accumulate).
// CTA tile 128x128, K-step 16, 256 threads = 8 warps in 4(M) x 2(N).
// Warp tile 32x64 = 2(M-atoms of 16) x 8(N-atoms of 8).
// ---------------------------------------------------------------------------
#define AS_STRIDE 20    // conflict-free A fragment loads (20g mod 32 covers all banks)
#define BS_STRIDE 136   // conflict-free B fragment loads

__global__ void __launch_bounds__(256) k_gemm(const float* __restrict__ Bw,
                                              float* __restrict__ Y) {
    __shared__ uint32_t As[128 * AS_STRIDE];   // [m][k], tf32 bits
    __shared__ uint32_t Bs[16 * BS_STRIDE];    // [k][n], tf32 bits

    const int tid  = threadIdx.x;
    const int lane = tid & 31;
    const int wid  = tid >> 5;
    const int wm   = wid & 3;        // 0..3  -> M offset wm*32
    const int wn   = wid >> 2;       // 0..1  -> N offset wn*64
    const int g    = lane >> 2;      // groupID
    const int t    = lane & 3;       // threadID_in_group

    const size_t m0 = (size_t)blockIdx.x * 128;
    const int    n0 = blockIdx.y * 128;

    // global->smem load mappings
    const int am = tid >> 1;               // 0..127 (A row)
    const int ak = (tid & 1) * 8;          // 0 or 8 (A k-chunk)
    const int bk = tid >> 4;               // 0..15  (B k row)
    const int bn = (tid & 15) * 8;         // 0..120 (B n-chunk)

    float c[2][8][4];
#pragma unroll
    for (int i = 0; i < 2; i++)
#pragma unroll
        for (int j = 0; j < 8; j++)
#pragma unroll
            for (int q = 0; q < 4; q++) c[i][j][q] = 0.f;

    for (int kk = 0; kk < 256; kk += 16) {
        // ---- load A tile [128 x 16] ----
        {
            const float* src = g_T + (m0 + am) * 256 + kk + ak;
            float4 v0 = *(const float4*)(src);
            float4 v1 = *(const float4*)(src + 4);
            uint32_t* d = &As[am * AS_STRIDE + ak];
            d[0] = f2tf32(v0.x); d[1] = f2tf32(v0.y);
            d[2] = f2tf32(v0.z); d[3] = f2tf32(v0.w);
            d[4] = f2tf32(v1.x); d[5] = f2tf32(v1.y);
            d[6] = f2tf32(v1.z); d[7] = f2tf32(v1.w);
        }
        // ---- load B tile [16 x 128] ----
        {
            const float* src = Bw + (size_t)(kk + bk) * 256 + n0 + bn;
            float4 v0 = *(const float4*)(src);
            float4 v1 = *(const float4*)(src + 4);
            uint32_t* d = &Bs[bk * BS_STRIDE + bn];
            d[0] = f2tf32(v0.x); d[1] = f2tf32(v0.y);
            d[2] = f2tf32(v0.z); d[3] = f2tf32(v0.w);
            d[4] = f2tf32(v1.x); d[5] = f2tf32(v1.y);
            d[6] = f2tf32(v1.z); d[7] = f2tf32(v1.w);
        }
        __syncthreads();

#pragma unroll
        for (int k0 = 0; k0 < 16; k0 += 8) {
            uint32_t a[2][4];
#pragma unroll
            for (int im = 0; im < 2; im++) {
                int rb = wm * 32 + im * 16;
                a[im][0] = As[(rb + g)     * AS_STRIDE + k0 + t];
                a[im][1] = As[(rb + g + 8) * AS_STRIDE + k0 + t];
                a[im][2] = As[(rb + g)     * AS_STRIDE + k0 + t + 4];
                a[im][3] = As[(rb + g + 8) * AS_STRIDE + k0 + t + 4];
            }
            uint32_t b[8][2];
#pragma unroll
            for (int in = 0; in < 8; in++) {
                int cb = wn * 64 + in * 8;
                b[in][0] = Bs[(k0 + t)     * BS_STRIDE + cb + g];
                b[in][1] = Bs[(k0 + t + 4) * BS_STRIDE + cb + g];
            }
#pragma unroll
            for (int im = 0; im < 2; im++)
#pragma unroll
                for (int in = 0; in < 8; in++) {
                    asm volatile(
                        "mma.sync.aligned.m16n8k8.row.col.f32.tf32.tf32.f32 "
                        "{%0,%1,%2,%3}, {%4,%5,%6,%7}, {%8,%9}, {%0,%1,%2,%3};"
                        : "+f"(c[im][in][0]), "+f"(c[im][in][1]),
                          "+f"(c[im][in][2]), "+f"(c[im][in][3])
                        : "r"(a[im][0]), "r"(a[im][1]), "r"(a[im][2]), "r"(a[im][3]),
                          "r"(b[in][0]), "r"(b[in][1]));
                }
        }
        __syncthreads();
    }

    // ---- epilogue: write C (pre-BN Y) into d_out ----
#pragma unroll
    for (int im = 0; im < 2; im++) {
        size_t r0 = m0 + wm * 32 + im * 16 + g;
#pragma unroll
        for (int in = 0; in < 8; in++) {
            int col = n0 + wn * 64 + in * 8 + 2 * t;
            *(float2*)(Y + r0 * 256 + col)       = make_float2(c[im][in][0], c[im][in][1]);
            *(float2*)(Y + (r0 + 8) * 256 + col) = make_float2(c[im][in][2], c[im][in][3]);
        }
    }
}

// ---------------------------------------------------------------------------
// K3: per-feature partial sums over a 128-batch slice (deterministic, no atomics)
// grid (40, NSPLIT), 256 threads (one per f)
// ---------------------------------------------------------------------------
__global__ void k_stats(const float* __restrict__ Y) {
    const int n  = blockIdx.x;
    const int f  = threadIdx.x;
    const int sp = blockIdx.y;
    const int b0 = sp * (BB / NSPLIT);
    float s = 0.f, s2 = 0.f;
    for (int b = b0; b < b0 + BB / NSPLIT; b++) {
        float v = Y[((size_t)b * NN + n) * FF + f];
        s  += v;
        s2 = fmaf(v, v, s2);
    }
    g_psum[sp * NF + n * FF + f]   = s;
    g_psumsq[sp * NF + n * FF + f] = s2;
}

// ---------------------------------------------------------------------------
// K3b: reduce partials, compute per-feature scale/shift.
// out = (Y - mean) * rsqrt(var+eps) * gamma[blk(n)]  +  sum_i beta[i]
// (rows outside block i contribute exactly beta[i] from that block's BN)
// ---------------------------------------------------------------------------
__global__ void k_finalize(const float* __restrict__ gamma,
                           const float* __restrict__ beta) {
    int i = blockIdx.x * blockDim.x + threadIdx.x;
    if (i >= NF) return;
    float s = 0.f, s2 = 0.f;
#pragma unroll 4
    for (int sp = 0; sp < NSPLIT; sp++) {
        s  += g_psum[sp * NF + i];
        s2 += g_psumsq[sp * NF + i];
    }
    const float inv = 1.f / (float)BB;
    float mean = s * inv;
    float var  = s2 * inv - mean * mean;
    int n   = i / FF;
    int blk = n / BLKSZ;
    float sc = rsqrtf(var + EPSF) * gamma[blk * NF + i];
    float sh = -mean * sc;
#pragma unroll
    for (int t = 0; t < NBLK; t++) sh += beta[t * NF + i];
    g_scale[i] = sc;
    g_shift[i] = sh;
}

// ---------------------------------------------------------------------------
// K4: out = Y * scale[nf] + shift[nf], in place on d_out, float4-vectorized
// ---------------------------------------------------------------------------
__global__ void k_norm(float* __restrict__ out) {
    size_t e = ((size_t)blockIdx.x * blockDim.x + threadIdx.x) * 4;
    if (e >= (size_t)BB * NN * FF) return;
    int nf = (int)(e % NF);      // NF divisible by 4 -> aligned
    float4 y  = *(const float4*)(out + e);
    float4 sc = *(const float4*)(g_scale + nf);
    float4 sh = *(const float4*)(g_shift + nf);
    float4 o;
    o.x = fmaf(y.x, sc.x, sh.x);
    o.y = fmaf(y.y, sc.y, sh.y);
    o.z = fmaf(y.z, sc.z, sh.z);
    o.w = fmaf(y.w, sc.w, sh.w);
    *(float4*)(out + e) = o;
}

// ---------------------------------------------------------------------------
extern "C" void kernel_launch(void* const* d_in, const int* in_sizes, int n_in,
                              void* d_out, int out_size) {
    const float* input = (const float*)d_in[0];   // [8192,40,256]
    const float* adj   = (const float*)d_in[1];   // [8192,40,40]
    const float* W     = (const float*)d_in[2];   // [256,256]
    const float* gamma = (const float*)d_in[3];   // [4,10240]
    const float* beta  = (const float*)d_in[4];   // [4,10240]
    float* out = (float*)d_out;                   // [8192,40,256]

    k_blockmix<<<dim3(BB, NBLK), 256>>>(input, adj);
    k_gemm<<<dim3((BB * NN) / 128, FF / 128), 256>>>(W, out);
    k_stats<<<dim3(NN, NSPLIT), 256>>>(out);
    k_finalize<<<(NF + 255) / 256, 256>>>(gamma, beta);
    {
        size_t tot4 = ((size_t)BB * NN * FF) / 4;
        int grid = (int)((tot4 + 255) / 256);
        k_norm<<<grid, 256>>>(out);
    }
}